// round 6
// baseline (speedup 1.0000x reference)
#include <cuda_runtime.h>
#include <cuda_bf16.h>
#include <cstdint>

#define RDIM 256
#define CDIM 32
#define NPTS 524288
#define THREADS 256
#define NWTILES (NPTS / 16)        // 32768 tiles of 16 points
#define NCONS 6                    // consumer warps per CTA
#define NPROD 2                    // producer warps per CTA

// Transposed triplanes scratch: [bp][y][x][c], fp32 (~100.7 MB)
__device__ float g_tp[(size_t)12 * RDIM * RDIM * CDIM];

// ---------------- smem layout (bytes) ----------------
// padded strides: 80 = 5*16, 272 = 17*16 (conflict-free ldmatrix rows)
#define OFF_W1HI 0                  // 128 rows * 272B
#define OFF_W1LO 34816
#define OFF_W0HI 69632              // 128 rows * 80B
#define OFF_W0LO 79872
#define OFF_F    90112              // 6 bufs * (16 rows*80B hi + 16 rows*80B lo)
#define FBUF_BYTES 2560
#define OFF_B0   105472             // 128 f32
#define OFF_B1   105984
#define OFF_W2   106496
#define SMEM_BYTES 107520

// ---------------- helpers ----------------
__device__ __forceinline__ uint32_t smem_u32(const void* p) {
    uint32_t a;
    asm("{ .reg .u64 t; cvta.to.shared.u64 t, %1; cvt.u32.u64 %0, t; }" : "=r"(a) : "l"(p));
    return a;
}
__device__ __forceinline__ void mma16816(float* d, const uint32_t* a, const uint32_t* b) {
    asm volatile("mma.sync.aligned.m16n8k16.row.col.f32.bf16.bf16.f32 "
                 "{%0,%1,%2,%3}, {%4,%5,%6,%7}, {%8,%9}, {%0,%1,%2,%3};"
                 : "+f"(d[0]), "+f"(d[1]), "+f"(d[2]), "+f"(d[3])
                 : "r"(a[0]), "r"(a[1]), "r"(a[2]), "r"(a[3]), "r"(b[0]), "r"(b[1]));
}
__device__ __forceinline__ void ldsm4(uint32_t* r, uint32_t addr) {
    asm volatile("ldmatrix.sync.aligned.m8n8.x4.shared.b16 {%0,%1,%2,%3}, [%4];"
                 : "=r"(r[0]), "=r"(r[1]), "=r"(r[2]), "=r"(r[3]) : "r"(addr));
}
__device__ __forceinline__ void split2(float v0, float v1, uint32_t& hi, uint32_t& lo) {
    asm("cvt.rn.bf16x2.f32 %0, %1, %2;" : "=r"(hi) : "f"(v1), "f"(v0));
    float f0 = __uint_as_float(hi << 16);
    float f1 = __uint_as_float(hi & 0xFFFF0000u);
    float r0 = v0 - f0, r1 = v1 - f1;
    asm("cvt.rn.bf16x2.f32 %0, %1, %2;" : "=r"(lo) : "f"(r1), "f"(r0));
}
__device__ __forceinline__ void barsync(int id) {
    asm volatile("bar.sync %0, 64;" :: "r"(id) : "memory");
}

// ---------- Kernel 1: transpose [bp][c][y][x] -> [bp][y][x][c] ----------
__global__ void transpose_planes(const float* __restrict__ in) {
    __shared__ float t[32][33];
    int tx = threadIdx.x, ty = threadIdx.y;
    int xb = blockIdx.x * 32, y = blockIdx.y, bp = blockIdx.z;
    const float* src = in + ((size_t)bp * CDIM) * (RDIM * RDIM) + (size_t)y * RDIM + xb;
#pragma unroll
    for (int i = 0; i < 4; i++) {
        int c = ty + i * 8;
        t[c][tx] = src[(size_t)c * (RDIM * RDIM) + tx];
    }
    __syncthreads();
    float* dst = g_tp + (((size_t)bp * RDIM + y) * RDIM + xb) * CDIM;
#pragma unroll
    for (int i = 0; i < 4; i++) {
        int xl = ty + i * 8;
        dst[(size_t)xl * CDIM + tx] = t[tx][xl];
    }
}

// ---------- Kernel 2: warp-specialized gather / bf16-MMA MLP ----------
__global__ __launch_bounds__(THREADS, 2)
void fused_triplane_mlp_ws(const float* __restrict__ coords,
                           const float* __restrict__ w0, const float* __restrict__ b0,
                           const float* __restrict__ w1, const float* __restrict__ b1,
                           const float* __restrict__ w2, const float* __restrict__ b2,
                           float* __restrict__ out) {
    extern __shared__ char sm[];
    const uint32_t sb = smem_u32(sm);
    const int tid = threadIdx.x;
    const int wid = tid >> 5;
    const int lane = tid & 31;

    float* sB0 = (float*)(sm + OFF_B0);
    float* sB1 = (float*)(sm + OFF_B1);
    float* sW2 = (float*)(sm + OFF_W2);

    // ---- stage weights: bf16 hi/lo split ----
    for (int i = tid; i < 16384; i += THREADS) {     // w1[g][h], stride 272B
        int g = i >> 7, h = i & 127;
        float v = w1[i];
        __nv_bfloat16 hb = __float2bfloat16(v);
        float res = v - __bfloat162float(hb);
        *(unsigned short*)(sm + OFF_W1HI + g * 272 + h * 2) = *(unsigned short*)&hb;
        __nv_bfloat16 lb = __float2bfloat16(res);
        *(unsigned short*)(sm + OFF_W1LO + g * 272 + h * 2) = *(unsigned short*)&lb;
    }
    for (int i = tid; i < 4096; i += THREADS) {      // w0[j][c], stride 80B
        int j = i >> 5, c = i & 31;
        float v = w0[i];
        __nv_bfloat16 hb = __float2bfloat16(v);
        float res = v - __bfloat162float(hb);
        *(unsigned short*)(sm + OFF_W0HI + j * 80 + c * 2) = *(unsigned short*)&hb;
        __nv_bfloat16 lb = __float2bfloat16(res);
        *(unsigned short*)(sm + OFF_W0LO + j * 80 + c * 2) = *(unsigned short*)&lb;
    }
    if (tid < 128) { sB0[tid] = b0[tid]; sB1[tid] = b1[tid]; sW2[tid] = w2[tid]; }
    const float bias2 = b2[0];
    __syncthreads();

    const int per_round = gridDim.x * NCONS;
    const int R = (NWTILES + per_round - 1) / per_round;

    if (wid < NPROD) {
        // ======================= PRODUCER =======================
        const int p = wid;
        const int pt_sub = lane >> 3;
        const int q = lane & 7;
        for (int r = 0; r < R; r++) {
#pragma unroll 1
            for (int j = 0; j < 3; j++) {
                const int c = 3 * p + j;
                const int t = (r * gridDim.x + blockIdx.x) * NCONS + c;
                if (t >= NWTILES) continue;
                if (r > 0) barsync(7 + c);            // wait buffer free
                char* bufhi = sm + OFF_F + c * FBUF_BYTES + (size_t)q * 8;
                char* buflo = bufhi + 1280;
                const int pbase = t * 16;
#pragma unroll 1
                for (int it = 0; it < 4; it++) {
                    const int row = it * 4 + pt_sub;
                    const int pt = pbase + row;
                    const float cx = coords[3 * pt + 0];
                    const float cy = coords[3 * pt + 1];
                    const float cz = coords[3 * pt + 2];
                    const int b = pt >> 17;
                    float4 acc;
#pragma unroll
                    for (int pl = 0; pl < 3; pl++) {
                        const float u = (pl == 1) ? cy : cx;
                        const float v = (pl == 0) ? cy : cz;
                        const float xf = (u + 1.0f) * 127.5f;
                        const float yf = (v + 1.0f) * 127.5f;
                        const float x0f = floorf(xf), y0f = floorf(yf);
                        const float wx = xf - x0f, wy = yf - y0f;
                        const int ix0 = (int)x0f, iy0 = (int)y0f;
                        const int ix1 = ix0 + 1, iy1 = iy0 + 1;
                        const float mx0 = (ix0 >= 0 && ix0 < RDIM) ? 1.0f : 0.0f;
                        const float mx1 = (ix1 >= 0 && ix1 < RDIM) ? 1.0f : 0.0f;
                        const float my0 = (iy0 >= 0 && iy0 < RDIM) ? 1.0f : 0.0f;
                        const float my1 = (iy1 >= 0 && iy1 < RDIM) ? 1.0f : 0.0f;
                        const int ix0c = min(max(ix0, 0), RDIM - 1);
                        const int ix1c = min(max(ix1, 0), RDIM - 1);
                        const int iy0c = min(max(iy0, 0), RDIM - 1);
                        const int iy1c = min(max(iy1, 0), RDIM - 1);
                        const float w00 = (1.0f - wx) * (1.0f - wy) * mx0 * my0;
                        const float w01 = wx * (1.0f - wy) * mx1 * my0;
                        const float w10 = (1.0f - wx) * wy * mx0 * my1;
                        const float w11 = wx * wy * mx1 * my1;
                        const float4* base =
                            (const float4*)(g_tp + ((size_t)(b * 3 + pl) * RDIM * RDIM) * CDIM);
                        const float4 a0 = base[(size_t)(iy0c * RDIM + ix0c) * 8 + q];
                        const float4 a1 = base[(size_t)(iy0c * RDIM + ix1c) * 8 + q];
                        const float4 a2 = base[(size_t)(iy1c * RDIM + ix0c) * 8 + q];
                        const float4 a3 = base[(size_t)(iy1c * RDIM + ix1c) * 8 + q];
                        float4 s;
                        s.x = w00 * a0.x + w01 * a1.x + w10 * a2.x + w11 * a3.x;
                        s.y = w00 * a0.y + w01 * a1.y + w10 * a2.y + w11 * a3.y;
                        s.z = w00 * a0.z + w01 * a1.z + w10 * a2.z + w11 * a3.z;
                        s.w = w00 * a0.w + w01 * a1.w + w10 * a2.w + w11 * a3.w;
                        if (pl == 0) acc = s;
                        else { acc.x *= s.x; acc.y *= s.y; acc.z *= s.z; acc.w *= s.w; }
                    }
                    uint2 hi, lo;
                    split2(acc.x, acc.y, hi.x, lo.x);
                    split2(acc.z, acc.w, hi.y, lo.y);
                    *(uint2*)(bufhi + row * 80) = hi;
                    *(uint2*)(buflo + row * 80) = lo;
                }
                barsync(1 + c);                       // publish buffer (drains STS)
            }
        }
    } else {
        // ======================= CONSUMER =======================
        const int c = wid - NPROD;
        const int grp = lane >> 3;
        const int idx = lane & 7;
        const uint32_t fA = (uint32_t)(OFF_F + c * FBUF_BYTES + (lane & 15) * 80 + (lane >> 4) * 16);
        const uint32_t aHI = sb + fA;
        const uint32_t aLO = aHI + 1280;
        const uint32_t b0off = (uint32_t)(((grp >> 1) * 8 + idx) * 80 + (grp & 1) * 16);
        const uint32_t w0HI = sb + OFF_W0HI + b0off;
        const uint32_t w0LO = sb + OFF_W0LO + b0off;
        const uint32_t b1off = (uint32_t)(((grp >> 1) * 8 + idx) * 272 + (grp & 1) * 16);
        const uint32_t w1HI = sb + OFF_W1HI + b1off;
        const uint32_t w1LO = sb + OFF_W1LO + b1off;
        const int c2 = 2 * (lane & 3);

        for (int r = 0; r < R; r++) {
            const int t = (r * gridDim.x + blockIdx.x) * NCONS + c;
            if (t >= NWTILES) continue;
            const int pbase = t * 16;
            barsync(1 + c);                           // wait buffer full

            // ---- layer 0 A fragments ----
            uint32_t A0h[2][4], A0l[2][4];
            ldsm4(A0h[0], aHI);  ldsm4(A0h[1], aHI + 32);
            ldsm4(A0l[0], aLO);  ldsm4(A0l[1], aLO + 32);

            uint32_t A1h[8][4], A1l[8][4];
            float D8[8][4];

#pragma unroll
            for (int nh = 0; nh < 2; nh++) {
#pragma unroll
                for (int m = 0; m < 8; m++) { D8[m][0]=0.f; D8[m][1]=0.f; D8[m][2]=0.f; D8[m][3]=0.f; }
#pragma unroll
                for (int ntp = 0; ntp < 4; ntp++) {
                    const uint32_t woff = (uint32_t)((nh * 4 + ntp) * (16 * 80));
#pragma unroll
                    for (int kf = 0; kf < 2; kf++) {
                        uint32_t bh[4], bl[4];
                        ldsm4(bh, w0HI + woff + kf * 32);
                        ldsm4(bl, w0LO + woff + kf * 32);
                        mma16816(D8[2 * ntp],     A0h[kf], bh);
                        mma16816(D8[2 * ntp],     A0h[kf], bl);
                        mma16816(D8[2 * ntp],     A0l[kf], bh);
                        mma16816(D8[2 * ntp + 1], A0h[kf], bh + 2);
                        mma16816(D8[2 * ntp + 1], A0h[kf], bl + 2);
                        mma16816(D8[2 * ntp + 1], A0l[kf], bh + 2);
                    }
                }
                if (nh == 0) {
                    // A0 fully consumed by the MMAs above -> release buffer for refill
                    if (t + per_round < NWTILES) barsync(7 + c);
                }
#pragma unroll
                for (int m = 0; m < 8; m++) {
                    const float2 bb = *(const float2*)(sB0 + nh * 64 + 8 * m + c2);
                    float v0 = fmaxf(D8[m][0] + bb.x, 0.f);
                    float v1 = fmaxf(D8[m][1] + bb.y, 0.f);
                    float v2 = fmaxf(D8[m][2] + bb.x, 0.f);
                    float v3 = fmaxf(D8[m][3] + bb.y, 0.f);
                    const int j = nh * 4 + (m >> 1), h = (m & 1) * 2;
                    split2(v0, v1, A1h[j][h],     A1l[j][h]);
                    split2(v2, v3, A1h[j][h + 1], A1l[j][h + 1]);
                }
            }

            // ---- layer 1 + layer 2, two n-halves ----
            float acc0 = 0.f, acc1 = 0.f;
#pragma unroll
            for (int oh = 0; oh < 2; oh++) {
#pragma unroll
                for (int m = 0; m < 8; m++) { D8[m][0]=0.f; D8[m][1]=0.f; D8[m][2]=0.f; D8[m][3]=0.f; }
#pragma unroll
                for (int ntp = 0; ntp < 4; ntp++) {
                    const uint32_t woff = (uint32_t)((oh * 4 + ntp) * (16 * 272));
#pragma unroll
                    for (int kf = 0; kf < 8; kf++) {
                        uint32_t bh[4], bl[4];
                        ldsm4(bh, w1HI + woff + kf * 32);
                        ldsm4(bl, w1LO + woff + kf * 32);
                        mma16816(D8[2 * ntp],     A1h[kf], bh);
                        mma16816(D8[2 * ntp],     A1h[kf], bl);
                        mma16816(D8[2 * ntp],     A1l[kf], bh);
                        mma16816(D8[2 * ntp + 1], A1h[kf], bh + 2);
                        mma16816(D8[2 * ntp + 1], A1h[kf], bl + 2);
                        mma16816(D8[2 * ntp + 1], A1l[kf], bh + 2);
                    }
                }
#pragma unroll
                for (int m = 0; m < 8; m++) {
                    const float2 bv = *(const float2*)(sB1 + oh * 64 + 8 * m + c2);
                    const float2 wv = *(const float2*)(sW2 + oh * 64 + 8 * m + c2);
                    acc0 = fmaf(fmaxf(D8[m][0] + bv.x, 0.f), wv.x, acc0);
                    acc0 = fmaf(fmaxf(D8[m][1] + bv.y, 0.f), wv.y, acc0);
                    acc1 = fmaf(fmaxf(D8[m][2] + bv.x, 0.f), wv.x, acc1);
                    acc1 = fmaf(fmaxf(D8[m][3] + bv.y, 0.f), wv.y, acc1);
                }
            }

            acc0 += __shfl_xor_sync(0xFFFFFFFFu, acc0, 1);
            acc0 += __shfl_xor_sync(0xFFFFFFFFu, acc0, 2);
            acc1 += __shfl_xor_sync(0xFFFFFFFFu, acc1, 1);
            acc1 += __shfl_xor_sync(0xFFFFFFFFu, acc1, 2);
            if ((lane & 3) == 0) {
                const int g = lane >> 2;
                out[pbase + g] = acc0 + bias2;
                out[pbase + g + 8] = acc1 + bias2;
            }
        }
    }
}

// ---------------- host ----------------
extern "C" void kernel_launch(void* const* d_in, const int* in_sizes, int n_in,
                              void* d_out, int out_size) {
    const float* triplanes = (const float*)d_in[0];
    const float* coords    = (const float*)d_in[1];
    const float* w0 = (const float*)d_in[2];
    const float* b0 = (const float*)d_in[3];
    const float* w1 = (const float*)d_in[4];
    const float* b1 = (const float*)d_in[5];
    const float* w2 = (const float*)d_in[6];
    const float* b2 = (const float*)d_in[7];
    float* out = (float*)d_out;

    dim3 tgrid(RDIM / 32, RDIM, 12);
    dim3 tblk(32, 8);
    transpose_planes<<<tgrid, tblk>>>(triplanes);

    static int sms = 0;
    if (sms == 0) {
        cudaDeviceGetAttribute(&sms, cudaDevAttrMultiProcessorCount, 0);
        cudaFuncSetAttribute(fused_triplane_mlp_ws,
                             cudaFuncAttributeMaxDynamicSharedMemorySize, SMEM_BYTES);
    }
    fused_triplane_mlp_ws<<<2 * sms, THREADS, SMEM_BYTES>>>(coords, w0, b0, w1, b1, w2, b2, out);
}

// round 7
// speedup vs baseline: 1.3808x; 1.3808x over previous
#include <cuda_runtime.h>
#include <cuda_bf16.h>
#include <cstdint>

#define RDIM 256
#define CDIM 32
#define NPTS 524288
#define THREADS 256
#define NWTILES (NPTS / 16)        // 32768 tiles of 16 points
#define NCONS 5                    // consumer warps per CTA
#define NPROD 3                    // producer warps per CTA

// Transposed triplanes scratch: [bp][y][x][c], fp32 (~100.7 MB)
__device__ float g_tp[(size_t)12 * RDIM * RDIM * CDIM];

// ---------------- smem layout (bytes) ----------------
// padded strides: 80 = 5*16, 272 = 17*16 (conflict-free ldmatrix rows)
#define OFF_W1HI 0                  // 128 rows * 272B
#define OFF_W1LO 34816
#define OFF_W0HI 69632              // 128 rows * 80B
#define OFF_W0LO 79872
#define OFF_F    90112              // 5 bufs * (16 rows*80B hi + 16 rows*80B lo)
#define FBUF_BYTES 2560
#define OFF_B0   102912             // 128 f32
#define OFF_B1   103424
#define OFF_W2   103936
#define SMEM_BYTES 104448

// ---------------- helpers ----------------
__device__ __forceinline__ uint32_t smem_u32(const void* p) {
    uint32_t a;
    asm("{ .reg .u64 t; cvta.to.shared.u64 t, %1; cvt.u32.u64 %0, t; }" : "=r"(a) : "l"(p));
    return a;
}
__device__ __forceinline__ void mma16816(float* d, const uint32_t* a, const uint32_t* b) {
    asm volatile("mma.sync.aligned.m16n8k16.row.col.f32.bf16.bf16.f32 "
                 "{%0,%1,%2,%3}, {%4,%5,%6,%7}, {%8,%9}, {%0,%1,%2,%3};"
                 : "+f"(d[0]), "+f"(d[1]), "+f"(d[2]), "+f"(d[3])
                 : "r"(a[0]), "r"(a[1]), "r"(a[2]), "r"(a[3]), "r"(b[0]), "r"(b[1]));
}
__device__ __forceinline__ void ldsm4(uint32_t* r, uint32_t addr) {
    asm volatile("ldmatrix.sync.aligned.m8n8.x4.shared.b16 {%0,%1,%2,%3}, [%4];"
                 : "=r"(r[0]), "=r"(r[1]), "=r"(r[2]), "=r"(r[3]) : "r"(addr));
}
__device__ __forceinline__ void split2(float v0, float v1, uint32_t& hi, uint32_t& lo) {
    asm("cvt.rn.bf16x2.f32 %0, %1, %2;" : "=r"(hi) : "f"(v1), "f"(v0));
    float f0 = __uint_as_float(hi << 16);
    float f1 = __uint_as_float(hi & 0xFFFF0000u);
    float r0 = v0 - f0, r1 = v1 - f1;
    asm("cvt.rn.bf16x2.f32 %0, %1, %2;" : "=r"(lo) : "f"(r1), "f"(r0));
}
__device__ __forceinline__ void bar_sync64(int id) {
    asm volatile("bar.sync %0, 64;" :: "r"(id) : "memory");
}
__device__ __forceinline__ void bar_arrive64(int id) {
    asm volatile("bar.arrive %0, 64;" :: "r"(id) : "memory");
}

// ---------- Kernel 1: transpose [bp][c][y][x] -> [bp][y][x][c] ----------
__global__ void transpose_planes(const float* __restrict__ in) {
    __shared__ float t[32][33];
    int tx = threadIdx.x, ty = threadIdx.y;
    int xb = blockIdx.x * 32, y = blockIdx.y, bp = blockIdx.z;
    const float* src = in + ((size_t)bp * CDIM) * (RDIM * RDIM) + (size_t)y * RDIM + xb;
#pragma unroll
    for (int i = 0; i < 4; i++) {
        int c = ty + i * 8;
        t[c][tx] = src[(size_t)c * (RDIM * RDIM) + tx];
    }
    __syncthreads();
    float* dst = g_tp + (((size_t)bp * RDIM + y) * RDIM + xb) * CDIM;
#pragma unroll
    for (int i = 0; i < 4; i++) {
        int xl = ty + i * 8;
        dst[(size_t)xl * CDIM + tx] = t[tx][xl];
    }
}

// ---------- Kernel 2: warp-specialized (3 prod / 5 cons), arrive/sync split ----------
__global__ __launch_bounds__(THREADS, 2)
void fused_triplane_mlp_ws2(const float* __restrict__ coords,
                            const float* __restrict__ w0, const float* __restrict__ b0,
                            const float* __restrict__ w1, const float* __restrict__ b1,
                            const float* __restrict__ w2, const float* __restrict__ b2,
                            float* __restrict__ out) {
    extern __shared__ char sm[];
    const uint32_t sb = smem_u32(sm);
    const int tid = threadIdx.x;
    const int wid = tid >> 5;
    const int lane = tid & 31;

    float* sB0 = (float*)(sm + OFF_B0);
    float* sB1 = (float*)(sm + OFF_B1);
    float* sW2 = (float*)(sm + OFF_W2);

    // ---- stage weights: bf16 hi/lo split ----
    for (int i = tid; i < 16384; i += THREADS) {     // w1[g][h], stride 272B
        int g = i >> 7, h = i & 127;
        float v = w1[i];
        __nv_bfloat16 hb = __float2bfloat16(v);
        float res = v - __bfloat162float(hb);
        *(unsigned short*)(sm + OFF_W1HI + g * 272 + h * 2) = *(unsigned short*)&hb;
        __nv_bfloat16 lb = __float2bfloat16(res);
        *(unsigned short*)(sm + OFF_W1LO + g * 272 + h * 2) = *(unsigned short*)&lb;
    }
    for (int i = tid; i < 4096; i += THREADS) {      // w0[j][c], stride 80B
        int j = i >> 5, c = i & 31;
        float v = w0[i];
        __nv_bfloat16 hb = __float2bfloat16(v);
        float res = v - __bfloat162float(hb);
        *(unsigned short*)(sm + OFF_W0HI + j * 80 + c * 2) = *(unsigned short*)&hb;
        __nv_bfloat16 lb = __float2bfloat16(res);
        *(unsigned short*)(sm + OFF_W0LO + j * 80 + c * 2) = *(unsigned short*)&lb;
    }
    if (tid < 128) { sB0[tid] = b0[tid]; sB1[tid] = b1[tid]; sW2[tid] = w2[tid]; }
    const float bias2 = b2[0];
    __syncthreads();

    const int per_round = gridDim.x * NCONS;
    const int R = (NWTILES + per_round - 1) / per_round;

    if (wid < NPROD) {
        // ======================= PRODUCER =======================
        const int p = wid;
        const int pt_sub = lane >> 3;
        const int q = lane & 7;
        const int nown = (p + 3 < NCONS) ? 2 : 1;     // p=0:{0,3} p=1:{1,4} p=2:{2}
        for (int r = 0; r < R; r++) {
#pragma unroll 1
            for (int j = 0; j < nown; j++) {
                const int c = p + 3 * j;
                const int t = (r * gridDim.x + blockIdx.x) * NCONS + c;
                if (t >= NWTILES) continue;
                if (r > 0) bar_sync64(9 + c);         // wait buffer free
                char* bufhi = sm + OFF_F + c * FBUF_BYTES + (size_t)q * 8;
                char* buflo = bufhi + 1280;
                const int pbase = t * 16;
#pragma unroll
                for (int it = 0; it < 4; it++) {
                    const int row = it * 4 + pt_sub;
                    const int pt = pbase + row;
                    const float cx = coords[3 * pt + 0];
                    const float cy = coords[3 * pt + 1];
                    const float cz = coords[3 * pt + 2];
                    const int b = pt >> 17;
                    float4 acc;
#pragma unroll
                    for (int pl = 0; pl < 3; pl++) {
                        const float u = (pl == 1) ? cy : cx;
                        const float v = (pl == 0) ? cy : cz;
                        const float xf = (u + 1.0f) * 127.5f;
                        const float yf = (v + 1.0f) * 127.5f;
                        const float x0f = floorf(xf), y0f = floorf(yf);
                        const float wx = xf - x0f, wy = yf - y0f;
                        const int ix0 = (int)x0f, iy0 = (int)y0f;
                        const int ix1 = ix0 + 1, iy1 = iy0 + 1;
                        const float mx0 = (ix0 >= 0 && ix0 < RDIM) ? 1.0f : 0.0f;
                        const float mx1 = (ix1 >= 0 && ix1 < RDIM) ? 1.0f : 0.0f;
                        const float my0 = (iy0 >= 0 && iy0 < RDIM) ? 1.0f : 0.0f;
                        const float my1 = (iy1 >= 0 && iy1 < RDIM) ? 1.0f : 0.0f;
                        const int ix0c = min(max(ix0, 0), RDIM - 1);
                        const int ix1c = min(max(ix1, 0), RDIM - 1);
                        const int iy0c = min(max(iy0, 0), RDIM - 1);
                        const int iy1c = min(max(iy1, 0), RDIM - 1);
                        const float w00 = (1.0f - wx) * (1.0f - wy) * mx0 * my0;
                        const float w01 = wx * (1.0f - wy) * mx1 * my0;
                        const float w10 = (1.0f - wx) * wy * mx0 * my1;
                        const float w11 = wx * wy * mx1 * my1;
                        const float4* base =
                            (const float4*)(g_tp + ((size_t)(b * 3 + pl) * RDIM * RDIM) * CDIM);
                        const float4 a0 = base[(size_t)(iy0c * RDIM + ix0c) * 8 + q];
                        const float4 a1 = base[(size_t)(iy0c * RDIM + ix1c) * 8 + q];
                        const float4 a2 = base[(size_t)(iy1c * RDIM + ix0c) * 8 + q];
                        const float4 a3 = base[(size_t)(iy1c * RDIM + ix1c) * 8 + q];
                        float4 s;
                        s.x = w00 * a0.x + w01 * a1.x + w10 * a2.x + w11 * a3.x;
                        s.y = w00 * a0.y + w01 * a1.y + w10 * a2.y + w11 * a3.y;
                        s.z = w00 * a0.z + w01 * a1.z + w10 * a2.z + w11 * a3.z;
                        s.w = w00 * a0.w + w01 * a1.w + w10 * a2.w + w11 * a3.w;
                        if (pl == 0) acc = s;
                        else { acc.x *= s.x; acc.y *= s.y; acc.z *= s.z; acc.w *= s.w; }
                    }
                    uint2 hi, lo;
                    split2(acc.x, acc.y, hi.x, lo.x);
                    split2(acc.z, acc.w, hi.y, lo.y);
                    *(uint2*)(bufhi + row * 80) = hi;
                    *(uint2*)(buflo + row * 80) = lo;
                }
                asm volatile("membar.cta;" ::: "memory");   // make STS visible
                bar_arrive64(1 + c);                        // publish (non-blocking)
            }
        }
    } else {
        // ======================= CONSUMER =======================
        const int c = wid - NPROD;
        const int grp = lane >> 3;
        const int idx = lane & 7;
        const uint32_t aHI = sb + (uint32_t)(OFF_F + c * FBUF_BYTES + (lane & 15) * 80 + (lane >> 4) * 16);
        const uint32_t aLO = aHI + 1280;
        const uint32_t b0off = (uint32_t)(((grp >> 1) * 8 + idx) * 80 + (grp & 1) * 16);
        const uint32_t w0HI = sb + OFF_W0HI + b0off;
        const uint32_t w0LO = sb + OFF_W0LO + b0off;
        const uint32_t b1off = (uint32_t)(((grp >> 1) * 8 + idx) * 272 + (grp & 1) * 16);
        const uint32_t w1HI = sb + OFF_W1HI + b1off;
        const uint32_t w1LO = sb + OFF_W1LO + b1off;
        const int c2 = 2 * (lane & 3);

        for (int r = 0; r < R; r++) {
            const int t = (r * gridDim.x + blockIdx.x) * NCONS + c;
            if (t >= NWTILES) continue;
            const int pbase = t * 16;
            bar_sync64(1 + c);                        // wait buffer full

            // ---- layer 0 A fragments ----
            uint32_t A0h[2][4], A0l[2][4];
            ldsm4(A0h[0], aHI);  ldsm4(A0h[1], aHI + 32);
            ldsm4(A0l[0], aLO);  ldsm4(A0l[1], aLO + 32);

            uint32_t A1h[8][4], A1l[8][4];
            float D8[8][4];

#pragma unroll
            for (int nh = 0; nh < 2; nh++) {
#pragma unroll
                for (int m = 0; m < 8; m++) { D8[m][0]=0.f; D8[m][1]=0.f; D8[m][2]=0.f; D8[m][3]=0.f; }
#pragma unroll
                for (int ntp = 0; ntp < 4; ntp++) {
                    const uint32_t woff = (uint32_t)((nh * 4 + ntp) * (16 * 80));
#pragma unroll
                    for (int kf = 0; kf < 2; kf++) {
                        uint32_t bh[4], bl[4];
                        ldsm4(bh, w0HI + woff + kf * 32);
                        ldsm4(bl, w0LO + woff + kf * 32);
                        mma16816(D8[2 * ntp],     A0h[kf], bh);
                        mma16816(D8[2 * ntp],     A0h[kf], bl);
                        mma16816(D8[2 * ntp],     A0l[kf], bh);
                        mma16816(D8[2 * ntp + 1], A0h[kf], bh + 2);
                        mma16816(D8[2 * ntp + 1], A0h[kf], bl + 2);
                        mma16816(D8[2 * ntp + 1], A0l[kf], bh + 2);
                    }
                }
                if (nh == 0) bar_arrive64(9 + c);     // A0 consumed -> release buffer
#pragma unroll
                for (int m = 0; m < 8; m++) {
                    const float2 bb = *(const float2*)(sB0 + nh * 64 + 8 * m + c2);
                    float v0 = fmaxf(D8[m][0] + bb.x, 0.f);
                    float v1 = fmaxf(D8[m][1] + bb.y, 0.f);
                    float v2 = fmaxf(D8[m][2] + bb.x, 0.f);
                    float v3 = fmaxf(D8[m][3] + bb.y, 0.f);
                    const int j = nh * 4 + (m >> 1), h = (m & 1) * 2;
                    split2(v0, v1, A1h[j][h],     A1l[j][h]);
                    split2(v2, v3, A1h[j][h + 1], A1l[j][h + 1]);
                }
            }

            // ---- layer 1 + layer 2, two n-halves ----
            float acc0 = 0.f, acc1 = 0.f;
#pragma unroll
            for (int oh = 0; oh < 2; oh++) {
#pragma unroll
                for (int m = 0; m < 8; m++) { D8[m][0]=0.f; D8[m][1]=0.f; D8[m][2]=0.f; D8[m][3]=0.f; }
#pragma unroll
                for (int ntp = 0; ntp < 4; ntp++) {
                    const uint32_t woff = (uint32_t)((oh * 4 + ntp) * (16 * 272));
#pragma unroll
                    for (int kf = 0; kf < 8; kf++) {
                        uint32_t bh[4], bl[4];
                        ldsm4(bh, w1HI + woff + kf * 32);
                        ldsm4(bl, w1LO + woff + kf * 32);
                        mma16816(D8[2 * ntp],     A1h[kf], bh);
                        mma16816(D8[2 * ntp],     A1h[kf], bl);
                        mma16816(D8[2 * ntp],     A1l[kf], bh);
                        mma16816(D8[2 * ntp + 1], A1h[kf], bh + 2);
                        mma16816(D8[2 * ntp + 1], A1h[kf], bl + 2);
                        mma16816(D8[2 * ntp + 1], A1l[kf], bh + 2);
                    }
                }
#pragma unroll
                for (int m = 0; m < 8; m++) {
                    const float2 bv = *(const float2*)(sB1 + oh * 64 + 8 * m + c2);
                    const float2 wv = *(const float2*)(sW2 + oh * 64 + 8 * m + c2);
                    acc0 = fmaf(fmaxf(D8[m][0] + bv.x, 0.f), wv.x, acc0);
                    acc0 = fmaf(fmaxf(D8[m][1] + bv.y, 0.f), wv.y, acc0);
                    acc1 = fmaf(fmaxf(D8[m][2] + bv.x, 0.f), wv.x, acc1);
                    acc1 = fmaf(fmaxf(D8[m][3] + bv.y, 0.f), wv.y, acc1);
                }
            }

            acc0 += __shfl_xor_sync(0xFFFFFFFFu, acc0, 1);
            acc0 += __shfl_xor_sync(0xFFFFFFFFu, acc0, 2);
            acc1 += __shfl_xor_sync(0xFFFFFFFFu, acc1, 1);
            acc1 += __shfl_xor_sync(0xFFFFFFFFu, acc1, 2);
            if ((lane & 3) == 0) {
                const int g = lane >> 2;
                out[pbase + g] = acc0 + bias2;
                out[pbase + g + 8] = acc1 + bias2;
            }
        }
    }
}

// ---------------- host ----------------
extern "C" void kernel_launch(void* const* d_in, const int* in_sizes, int n_in,
                              void* d_out, int out_size) {
    const float* triplanes = (const float*)d_in[0];
    const float* coords    = (const float*)d_in[1];
    const float* w0 = (const float*)d_in[2];
    const float* b0 = (const float*)d_in[3];
    const float* w1 = (const float*)d_in[4];
    const float* b1 = (const float*)d_in[5];
    const float* w2 = (const float*)d_in[6];
    const float* b2 = (const float*)d_in[7];
    float* out = (float*)d_out;

    dim3 tgrid(RDIM / 32, RDIM, 12);
    dim3 tblk(32, 8);
    transpose_planes<<<tgrid, tblk>>>(triplanes);

    static int sms = 0;
    if (sms == 0) {
        cudaDeviceGetAttribute(&sms, cudaDevAttrMultiProcessorCount, 0);
        cudaFuncSetAttribute(fused_triplane_mlp_ws2,
                             cudaFuncAttributeMaxDynamicSharedMemorySize, SMEM_BYTES);
    }
    fused_triplane_mlp_ws2<<<2 * sms, THREADS, SMEM_BYTES>>>(coords, w0, b0, w1, b1, w2, b2, out);
}